// round 5
// baseline (speedup 1.0000x reference)
#include <cuda_runtime.h>
#include <cuda_fp16.h>

// TrainableActivation (per-channel RBF activation) on GB300 — round 5.
//
// out[n,c,h,w] = sum_{j=0..30} w[c,j] * exp(-112.5 * (x - mu_j)^2)
//
// Round-5 changes vs round 4 (apply 19.55us, DRAM 52.5%, L1 66.6%):
//  * Tile smem staging (cp.async + LDS.128 readback) DELETED — it was ~43%
//    of the L1 wavefront work. Inputs now stream through a depth-3 REGISTER
//    pipeline (float4 vb[3], fully unrolled): 3 outstanding LDG.128/warp
//    x 48 warps/SM ~ 74KB in flight >> 25KB Little's-law requirement.
//  * smem: 16KB replicated LUT + 4KB staging = 20KB -> 6 blocks/SM.
//  * LUT unchanged: 1024-entry half2 (value,delta), 4-way bank-replicated.

#define NUM_CH   64
#define NUM_W    31
#define LUT_N    1024
#define REP      4
#define HW       16384    // 128*128
#define NBATCH   16

#define XLO  (-1.5f)
#define XHI  ( 1.5f)

#define TILE_F4       256      // float4 per tile == blockDim
#define TILES_PER_BLK 8        // half plane: 2048 float4 / 256
#define DEPTH         3        // register pipeline depth

// 64 * 1024 * 4B = 256 KB compact LUT (L2-resident after build).
__device__ __align__(16) __half2 g_lut[NUM_CH][LUT_N];

// ---------------------------------------------------------------------------
// Kernel 1: build the compact per-channel LUT. Grid (64, 4): block (c, seg)
// computes 256 entries. Entry i packs (f(x_i), f(x_{i+1})-f(x_i)) as half2.
// ---------------------------------------------------------------------------
__global__ __launch_bounds__(256) void build_lut_kernel(const float* __restrict__ w)
{
    __shared__ float sf[257];
    const int c    = blockIdx.x;
    const int base = blockIdx.y * 256;
    const int tid  = threadIdx.x;

    float wreg[NUM_W];
#pragma unroll
    for (int j = 0; j < NUM_W; j++) wreg[j] = w[c * NUM_W + j];

    const float h = (XHI - XLO) / (float)(LUT_N - 1);

    for (int k = tid; k < 257; k += 256) {
        const int i = base + k;
        float s = 0.0f;
        if (i < LUT_N) {
            const float x = XLO + (float)i * h;
#pragma unroll
            for (int j = 0; j < NUM_W; j++) {
                const float mu = -1.0f + (float)j * (2.0f / 30.0f);
                const float u = x - mu;
                s += wreg[j] * __expf(-112.5f * u * u);
            }
        }
        sf[k] = s;
    }
    __syncthreads();

    const int i = base + tid;
    const float d = (i < LUT_N - 1) ? (sf[tid + 1] - sf[tid]) : 0.0f;
    g_lut[c][i] = __floats2half2_rn(sf[tid], d);   // .x = value, .y = delta
}

// ---------------------------------------------------------------------------
// Kernel 2: apply. Grid (64, 16, 2): block (c, n, z) processes half of
// x[n][c][:][:] (2048 float4) via a depth-3 register pipeline + smem LUT.
// ---------------------------------------------------------------------------
__device__ __forceinline__ void cp16(void* dst_smem, const void* src_gmem)
{
    unsigned d = (unsigned)__cvta_generic_to_shared(dst_smem);
    asm volatile("cp.async.cg.shared.global [%0], [%1], 16;" :: "r"(d), "l"(src_gmem));
}

__global__ void __launch_bounds__(256, 6) apply_lut_kernel(const float4* __restrict__ x,
                                                           float4* __restrict__ y)
{
    __shared__ __align__(16) __half2 lut[LUT_N * REP];   // 16 KB replicated
    __shared__ __align__(16) __half2 compact[LUT_N];     //  4 KB staging

    const int c   = blockIdx.x;
    const int n   = blockIdx.y;
    const int z   = blockIdx.z;
    const int tid = threadIdx.x;

    const int base = (n * NUM_CH + c) * (HW / 4) + z * (TILES_PER_BLK * TILE_F4);
    const float4* src = x + base;
    float4*       dst = y + base;

    // Stage the compact 4 KB LUT via cp.async (frees the front-end to issue
    // the input LDGs below immediately).
    cp16(&compact[tid * 4], &g_lut[c][tid * 4]);
    asm volatile("cp.async.commit_group;");

    // Prologue of the register pipeline: first DEPTH tiles in flight.
    float4 vb[DEPTH];
#pragma unroll
    for (int t = 0; t < DEPTH; t++)
        vb[t] = __ldcs(src + t * TILE_F4 + tid);

    // LUT landed -> publish and expand 4-way (entry i -> words 4i..4i+3).
    asm volatile("cp.async.wait_group 0;" ::: "memory");
    __syncthreads();
    {
        const unsigned* cw = reinterpret_cast<const unsigned*>(compact);
        uint4* lr = reinterpret_cast<uint4*>(lut);
#pragma unroll
        for (int m = 0; m < LUT_N / 256; m++) {
            const unsigned u = cw[tid + 256 * m];        // conflict-free LDS.32
            lr[tid + 256 * m] = make_uint4(u, u, u, u);  // consecutive STS.128
        }
    }
    __syncthreads();   // only barrier; main loop is barrier-free

    const float INV_H = (float)(LUT_N - 1) / (XHI - XLO);
    const float OFF   = -XLO * INV_H;
    const float TMAX  = (float)(LUT_N - 1);

    // Lane reads its own replica: word index = idx*REP + (lane&3).
    const __half2* lp = lut + (tid & 3);

#pragma unroll
    for (int t = 0; t < TILES_PER_BLK; t++) {
        const float4 v = vb[t % DEPTH];
        if (t + DEPTH < TILES_PER_BLK)                    // refill the slot
            vb[t % DEPTH] = __ldcs(src + (t + DEPTH) * TILE_F4 + tid);

        float4 o;
        {
            const float tt = fminf(fmaxf(fmaf(v.x, INV_H, OFF), 0.0f), TMAX);
            const int idx = (int)tt;
            const float2 e = __half22float2(lp[idx * REP]);
            o.x = fmaf(tt - (float)idx, e.y, e.x);
        }
        {
            const float tt = fminf(fmaxf(fmaf(v.y, INV_H, OFF), 0.0f), TMAX);
            const int idx = (int)tt;
            const float2 e = __half22float2(lp[idx * REP]);
            o.y = fmaf(tt - (float)idx, e.y, e.x);
        }
        {
            const float tt = fminf(fmaxf(fmaf(v.z, INV_H, OFF), 0.0f), TMAX);
            const int idx = (int)tt;
            const float2 e = __half22float2(lp[idx * REP]);
            o.z = fmaf(tt - (float)idx, e.y, e.x);
        }
        {
            const float tt = fminf(fmaxf(fmaf(v.w, INV_H, OFF), 0.0f), TMAX);
            const int idx = (int)tt;
            const float2 e = __half22float2(lp[idx * REP]);
            o.w = fmaf(tt - (float)idx, e.y, e.x);
        }

        __stcs(dst + t * TILE_F4 + tid, o);
    }
}

// ---------------------------------------------------------------------------
// Launch: two dependent kernels (graph-capturable, allocation-free).
// ---------------------------------------------------------------------------
extern "C" void kernel_launch(void* const* d_in, const int* in_sizes, int n_in,
                              void* d_out, int out_size)
{
    const float* x = (const float*)d_in[0];   // [16, 64, 128, 128] fp32
    const float* w = (const float*)d_in[1];   // [64, 31] fp32

    build_lut_kernel<<<dim3(NUM_CH, LUT_N / 256), 256>>>(w);

    apply_lut_kernel<<<dim3(NUM_CH, NBATCH, 2), 256>>>(
        reinterpret_cast<const float4*>(x),
        reinterpret_cast<float4*>(d_out));
}

// round 6
// speedup vs baseline: 1.0141x; 1.0141x over previous
#include <cuda_runtime.h>
#include <cuda_fp16.h>

// TrainableActivation (per-channel RBF activation) on GB300 — round 6.
//
// out[n,c,h,w] = sum_{j=0..30} w[c,j] * exp(-112.5 * (x - mu_j)^2)
//
// Round-6: ONE fused kernel, fully-resident grid.
//  * LUT build fused into the apply kernel (windowed Gaussian sum, <=11
//    active centers per entry) -> kills the build kernel + graph gap (5.5us).
//  * grid (64,16) = 1024 blocks, launch_bounds(256,7): 148*7=1036 >= 1024,
//    ALL blocks resident in a single wave, no tail.
//  * LUT compute overlaps the depth-3 register-pipeline prologue LDGs.
//  * 1024-entry half2 (value,delta) LUT, 4-way bank-replicated in smem.

#define NUM_CH   64
#define NUM_W    31
#define LUT_N    1024
#define REP      4
#define HW       16384    // 128*128
#define NBATCH   16

#define TILE_F4       256      // float4 per tile == blockDim
#define TILES_PER_BLK 16       // one full plane: 4096 float4
#define DEPTH         3        // register pipeline depth

__global__ void __launch_bounds__(256, 7)
fused_rbf_kernel(const float4* __restrict__ x,
                 float4* __restrict__ y,
                 const float* __restrict__ w)
{
    __shared__ __align__(16) __half2 lut[LUT_N * REP];  // 16 KB replicated
    __shared__ float fv[LUT_N + 4];                     //  4 KB raw values
    __shared__ float ws[NUM_W];

    const int c   = blockIdx.x;
    const int n   = blockIdx.y;
    const int tid = threadIdx.x;

    const int base = (n * NUM_CH + c) * (HW / 4);
    const float4* src = x + base;
    float4*       dst = y + base;

    // ---- Prologue: get DRAM going before anything else -------------------
    float4 vb[DEPTH];
#pragma unroll
    for (int t = 0; t < DEPTH; t++)
        vb[t] = src[t * TILE_F4 + tid];

    // ---- Build this channel's LUT in smem (overlaps the LDG latency) -----
    if (tid < NUM_W) ws[tid] = w[c * NUM_W + tid];
    __syncthreads();

    // f(x) at 1025 points over [-1.5, 1.5]; only centers with |x-mu|<=0.36
    // contribute above 5e-7 (sigma=1/15, exp(-112.5*0.36^2)=4.6e-7).
    const float h = 3.0f / (float)(LUT_N - 1);
    for (int k = tid; k < LUT_N + 1; k += 256) {
        const float xx = -1.5f + (float)k * h;
        int j0 = (int)ceilf((xx + 0.64f) * 15.0f);   // first center >= xx-0.36
        j0 = max(j0, 0);
        float s = 0.0f;
#pragma unroll
        for (int m = 0; m < 11; m++) {
            const int j = j0 + m;
            const float mu = -1.0f + (float)j * (1.0f / 15.0f);
            const float u = xx - mu;
            const float g = __expf(-112.5f * u * u);
            s += (j < NUM_W) ? ws[j] * g : 0.0f;
        }
        fv[k] = s;
    }
    __syncthreads();

    // Pack (value, forward-delta) as half2 and replicate 4-way:
    // entry i occupies words 4i..4i+3 (lane reads copy lane&3).
#pragma unroll
    for (int m = 0; m < LUT_N / 256; m++) {
        const int i = tid + 256 * m;
        __half2 e = __floats2half2_rn(fv[i], fv[i + 1] - fv[i]);
        const unsigned u = *reinterpret_cast<unsigned*>(&e);
        reinterpret_cast<uint4*>(lut)[i] = make_uint4(u, u, u, u);
    }
    __syncthreads();   // last barrier; main loop is barrier-free

    // ---- Main loop: 16 tiles through the register pipeline ---------------
    const float INV_H = (float)(LUT_N - 1) / 3.0f;
    const float OFF   = 1.5f * INV_H;
    const float TMAX  = (float)(LUT_N - 1);

    const __half2* lp = lut + (tid & 3);

#pragma unroll
    for (int t = 0; t < TILES_PER_BLK; t++) {
        const float4 v = vb[t % DEPTH];
        if (t + DEPTH < TILES_PER_BLK)                    // refill the slot
            vb[t % DEPTH] = src[(t + DEPTH) * TILE_F4 + tid];

        float4 o;
        {
            const float tt = fminf(fmaxf(fmaf(v.x, INV_H, OFF), 0.0f), TMAX);
            const int idx = (int)tt;
            const float2 e = __half22float2(lp[idx * REP]);
            o.x = fmaf(tt - (float)idx, e.y, e.x);
        }
        {
            const float tt = fminf(fmaxf(fmaf(v.y, INV_H, OFF), 0.0f), TMAX);
            const int idx = (int)tt;
            const float2 e = __half22float2(lp[idx * REP]);
            o.y = fmaf(tt - (float)idx, e.y, e.x);
        }
        {
            const float tt = fminf(fmaxf(fmaf(v.z, INV_H, OFF), 0.0f), TMAX);
            const int idx = (int)tt;
            const float2 e = __half22float2(lp[idx * REP]);
            o.z = fmaf(tt - (float)idx, e.y, e.x);
        }
        {
            const float tt = fminf(fmaxf(fmaf(v.w, INV_H, OFF), 0.0f), TMAX);
            const int idx = (int)tt;
            const float2 e = __half22float2(lp[idx * REP]);
            o.w = fmaf(tt - (float)idx, e.y, e.x);
        }

        __stcs(dst + t * TILE_F4 + tid, o);
    }
}

// ---------------------------------------------------------------------------
// Launch: ONE kernel (graph-capturable, allocation-free, deterministic).
// ---------------------------------------------------------------------------
extern "C" void kernel_launch(void* const* d_in, const int* in_sizes, int n_in,
                              void* d_out, int out_size)
{
    const float* x = (const float*)d_in[0];   // [16, 64, 128, 128] fp32
    const float* w = (const float*)d_in[1];   // [64, 31] fp32

    fused_rbf_kernel<<<dim3(NUM_CH, NBATCH), 256>>>(
        reinterpret_cast<const float4*>(x),
        reinterpret_cast<float4*>(d_out),
        w);
}

// round 7
// speedup vs baseline: 1.1931x; 1.1765x over previous
#include <cuda_runtime.h>
#include <cuda_fp16.h>

// TrainableActivation (per-channel RBF activation) on GB300 — round 7.
//
// out[n,c,h,w] = sum_{j=0..30} w[c,j] * exp(-112.5 * (x - mu_j)^2)
//
// Round-7 changes vs round 6 (fused 22.66us; in-block LUT build cost ~2.9us):
//  * LUT build uses the Gaussian lattice recurrence (sigma == spacing):
//      g_{j+1} = g_j * r_j,  r_{j+1} = r_j * exp(-1)
//    -> 2 __expf + 11 fma-pairs per entry instead of 11 __expf (5.5x less MUFU).
//  * LUT_N 1024 -> 512 (interp err ~1.2e-4, fp16 err 2.1e-4 dominates; total
//    ~3e-4 vs 1e-3 gate). Halves build work and replicated-LUT smem (8 KB).
//  * Everything else kept: single fused kernel, fully-resident 1024-block
//    wave, depth-3 register input pipeline, 4-way bank-replicated gather,
//    streaming stores.

#define NUM_CH   64
#define NUM_W    31
#define LUT_N    512
#define REP      4
#define HW       16384    // 128*128
#define NBATCH   16

#define TILE_F4       256      // float4 per tile == blockDim
#define TILES_PER_BLK 16       // one full plane: 4096 float4
#define DEPTH         3        // register pipeline depth

__global__ void __launch_bounds__(256, 7)
fused_rbf_kernel(const float4* __restrict__ x,
                 float4* __restrict__ y,
                 const float* __restrict__ w)
{
    __shared__ __align__(16) __half2 lut[LUT_N * REP];  // 8 KB replicated
    __shared__ float fv[LUT_N + 1];                     // 2 KB raw values
    __shared__ float ws[NUM_W];

    const int c   = blockIdx.x;
    const int n   = blockIdx.y;
    const int tid = threadIdx.x;

    const int base = (n * NUM_CH + c) * (HW / 4);
    const float4* src = x + base;
    float4*       dst = y + base;

    // ---- Prologue: get DRAM going before anything else -------------------
    float4 vb[DEPTH];
#pragma unroll
    for (int t = 0; t < DEPTH; t++)
        vb[t] = src[t * TILE_F4 + tid];

    // ---- Build this channel's LUT in smem (overlaps the LDG latency) -----
    if (tid < NUM_W) ws[tid] = w[c * NUM_W + tid];
    __syncthreads();

    // f at 513 points over [-1.5, 1.5]. Window: 11 centers nearest x
    // (terms outside |x-mu|>0.36 are < 5e-7). Inside the window use the
    // lattice recurrence: a=112.5, delta=1/15 ->
    //   g_j = exp(-a*u_j^2), r_j = exp(15*u_j - 0.5), r_{j+1} = r_j*e^-1.
    const float h = 3.0f / (float)(LUT_N - 1);
    for (int k = tid; k < LUT_N + 1; k += 256) {
        const float xx = fmaf((float)k, h, -1.5f);
        const float t  = (xx + 1.0f) * 15.0f;            // spacing units
        int j0 = (int)ceilf(t - 5.4f);
        j0 = min(20, max(0, j0));
        const float u0 = xx - fmaf((float)j0, 1.0f / 15.0f, -1.0f);

        float g = __expf(-112.5f * u0 * u0);
        float r = __expf(fmaf(15.0f, u0, -0.5f));
        float s = 0.0f;
#pragma unroll
        for (int m = 0; m < 11; m++) {
            s = fmaf(ws[j0 + m], g, s);
            g *= r;
            r *= 0.36787944f;    // e^-1
        }
        fv[k] = s;
    }
    __syncthreads();

    // Pack (value, forward-delta) as half2 and replicate 4-way:
    // entry i occupies words 4i..4i+3 (lane reads copy lane&3).
#pragma unroll
    for (int m = 0; m < LUT_N / 256; m++) {
        const int i = tid + 256 * m;
        __half2 e = __floats2half2_rn(fv[i], fv[i + 1] - fv[i]);
        const unsigned u = *reinterpret_cast<unsigned*>(&e);
        reinterpret_cast<uint4*>(lut)[i] = make_uint4(u, u, u, u);
    }
    __syncthreads();   // last barrier; main loop is barrier-free

    // ---- Main loop: 16 tiles through the register pipeline ---------------
    const float INV_H = (float)(LUT_N - 1) / 3.0f;
    const float OFF   = 1.5f * INV_H;
    const float TMAX  = (float)(LUT_N - 1);

    const __half2* lp = lut + (tid & 3);

#pragma unroll
    for (int t = 0; t < TILES_PER_BLK; t++) {
        const float4 v = vb[t % DEPTH];
        if (t + DEPTH < TILES_PER_BLK)                    // refill the slot
            vb[t % DEPTH] = src[(t + DEPTH) * TILE_F4 + tid];

        float4 o;
        {
            const float tt = fminf(fmaxf(fmaf(v.x, INV_H, OFF), 0.0f), TMAX);
            const int idx = (int)tt;
            const float2 e = __half22float2(lp[idx * REP]);
            o.x = fmaf(tt - (float)idx, e.y, e.x);
        }
        {
            const float tt = fminf(fmaxf(fmaf(v.y, INV_H, OFF), 0.0f), TMAX);
            const int idx = (int)tt;
            const float2 e = __half22float2(lp[idx * REP]);
            o.y = fmaf(tt - (float)idx, e.y, e.x);
        }
        {
            const float tt = fminf(fmaxf(fmaf(v.z, INV_H, OFF), 0.0f), TMAX);
            const int idx = (int)tt;
            const float2 e = __half22float2(lp[idx * REP]);
            o.z = fmaf(tt - (float)idx, e.y, e.x);
        }
        {
            const float tt = fminf(fmaxf(fmaf(v.w, INV_H, OFF), 0.0f), TMAX);
            const int idx = (int)tt;
            const float2 e = __half22float2(lp[idx * REP]);
            o.w = fmaf(tt - (float)idx, e.y, e.x);
        }

        __stcs(dst + t * TILE_F4 + tid, o);
    }
}

// ---------------------------------------------------------------------------
// Launch: ONE kernel (graph-capturable, allocation-free, deterministic).
// ---------------------------------------------------------------------------
extern "C" void kernel_launch(void* const* d_in, const int* in_sizes, int n_in,
                              void* d_out, int out_size)
{
    const float* x = (const float*)d_in[0];   // [16, 64, 128, 128] fp32
    const float* w = (const float*)d_in[1];   // [64, 31] fp32

    fused_rbf_kernel<<<dim3(NUM_CH, NBATCH), 256>>>(
        reinterpret_cast<const float4*>(x),
        reinterpret_cast<float4*>(d_out),
        w);
}